// round 15
// baseline (speedup 1.0000x reference)
#include <cuda_runtime.h>
#include <cuda_bf16.h>

#define RIR_LEN   8000
#define NIMG      1561
#define NSPLIT    7
#define NTH       512
#define NWARP     (NTH / 32)
#define PI_F      3.14159265358979323846f
#define INV_PI_F  0.3183098861837907f
#define FS_OVER_C 46.64723032069971f   /* 16000 / 343 */

// ---------------------------------------------------------------------------
// Per-(room, image-range) partial RIR in shared memory, RED.ADD into out.
// out RIR region must be pre-zeroed (memset node in kernel_launch).
// ---------------------------------------------------------------------------
__global__ void __launch_bounds__(NTH, 3)
rir_partial_kernel(const float* __restrict__ in, float* __restrict__ out, int B)
{
    __shared__ float srir[RIR_LEN];     // 32000 B
    __shared__ float prm[10];
    __shared__ float roomS[3], micS[3], srcS[3];
    __shared__ float trp[11];           // tr^k
    __shared__ int   pfx[22];           // image-index prefix per gx shell

    const int b    = blockIdx.x / NSPLIT;   // room
    const int sub  = blockIdx.x % NSPLIT;   // image-range split
    const int tid  = threadIdx.x;
    const int lane = tid & 31;
    const int warp = tid >> 5;

    if (tid < 10) prm[tid] = in[b * 10 + tid];
    if (tid < 22) {
        int n = tid, v;
        if (n <= 10) v = (n - 1) * n * (2 * n - 1) / 3 + (n - 1) * n + n;
        else { int m = 21 - n; v = NIMG - ((m - 1) * m * (2 * m - 1) / 3 + (m - 1) * m + m); }
        pfx[tid] = v;
    }
    {
        float4* s4 = (float4*)srir;
        for (int i = tid; i < RIR_LEN / 4; i += NTH)
            s4[i] = make_float4(0.f, 0.f, 0.f, 0.f);
    }
    __syncthreads();

    if (tid < 3) {
        float r = prm[tid];
        roomS[tid] = r;
        micS[tid]  = prm[3 + tid] * r;
        srcS[tid]  = prm[6 + tid] * r;
    }
    if (tid < 11) trp[tid] = powf(sqrtf(1.0f - prm[9]), (float)tid);

    // Register-resident Hann window basis for this lane's 3 tap slots:
    // (cos, -sin)(pi*(t-40)/40) at t = lane, lane+32, lane+64.
    const float tmf0 = (float)(lane - 40);
    const float tmf1 = (float)(lane - 8);
    const float tmf2 = (float)(lane + 24);
    float c0, ns0, c1, ns1, c2, ns2, sv;
    sincosf(PI_F * (1.0f / 40.0f) * tmf0, &sv, &c0); ns0 = -sv;
    sincosf(PI_F * (1.0f / 40.0f) * tmf1, &sv, &c1); ns1 = -sv;
    sincosf(PI_F * (1.0f / 40.0f) * tmf2, &sv, &c2); ns2 = -sv;
    const float sgn = (lane & 1) ? -1.0f : 1.0f;   // (-1)^t, t = lane+32r
    __syncthreads();

    // image sub-range for this CTA, chunked evenly over warps
    const int is    = (NIMG * sub)       / NSPLIT;
    const int ie    = (NIMG * (sub + 1)) / NSPLIT;
    const int chunk = (ie - is + NWARP - 1) / NWARP;
    const int ws    = min(is + warp * chunk, ie);
    const int we    = min(ws + chunk, ie);

    for (int i0 = ws; i0 < we; i0 += 32) {
        const int i = i0 + lane;

        // ---------- lane-parallel per-image scalar phase ----------
        float frL = 0.0f, a2L = 0.0f, hcL = 0.0f, hsL = 0.0f;
        int   baseL = RIR_LEN;
        if (i < we) {
            // decode image index -> (gx, gy, gz), |gx|+|gy|+|gz| <= 10
            int lo = 0, hi = 21;
#pragma unroll
            for (int it = 0; it < 5; it++) {
                int mid = (lo + hi) >> 1;
                if (i >= pfx[mid]) lo = mid; else hi = mid;
            }
            const int gx = lo - 10;
            const int ax = gx < 0 ? -gx : gx;
            const int R  = 10 - ax;
            const int j  = i - pfx[lo];
            const int M  = 2 * R * R + 2 * R + 1;
            const int rp1 = R + 1;
            int k;
            if (j < rp1 * rp1) k = (int)sqrtf((float)j + 0.5f);
            else               k = 2 * R - (int)sqrtf((float)(M - 1 - j) + 0.5f);
            const int Pk = (k <= R) ? k * k : M - (2 * R + 1 - k) * (2 * R + 1 - k);
            const int gy = k - R;
            const int ay = gy < 0 ? -gy : gy;
            const int gz = (j - Pk) - (R - ay);
            const int az = gz < 0 ? -gz : gz;

            const float att = trp[ax + ay + az];
            const int g3[3] = {gx, gy, gz};
            float d2 = 0.0f;
#pragma unroll
            for (int d = 0; d < 3; d++) {
                const int   g  = g3[d];
                const float gf = (float)g;
                const float ip = (g & 1) ? roomS[d] * (gf + 1.0f) - srcS[d]
                                         : roomS[d] * gf + srcS[d];
                const float df = ip - micS[d];
                d2 += df * df;
            }
            const float dist    = sqrtf(d2);
            const float amp     = __fdividef(att, dist);
            const float delay   = dist * FS_OVER_C;
            const float delay_i = ceilf(delay);
            // clamp frac away from 0: sin(pi*fr)/(pi*x) reproduces sinc(0)=1
            // to ~1e-9 abs, so no x==0 special case needed
            const float fr = fmaxf(delay_i - delay, 1e-9f);

            // must be ACCURATE sinf: __sinf's absolute error (~4e-7) blows up
            // when divided by pi*fr with fr ~ 1e-9 (R10 failure)
            const float s = sinf(PI_F * fr);       // sin(pi*x) = s*(-1)^t
            float sA, cA;
            __sincosf(PI_F * (1.0f / 40.0f) * fr, &sA, &cA);

            frL   = fr;
            a2L   = amp * s * INV_PI_F;
            hcL   = 0.5f * cA;
            hsL   = 0.5f * sA;
            baseL = (int)delay_i - 40;
        }

        // ---------- warp-cooperative tap scatter (conflict-free) ----------
        const int nv = min(32, we - i0);
        for (int jj = 0; jj < nv; jj++) {
            const int base = __shfl_sync(0xffffffffu, baseL, jj);
            if (base >= RIR_LEN) continue;         // fully clipped image
            const float fr = __shfl_sync(0xffffffffu, frL, jj);
            const float a2 = __shfl_sync(0xffffffffu, a2L, jj);
            const float hc = __shfl_sync(0xffffffffu, hcL, jj);
            const float hs = __shfl_sync(0xffffffffu, hsL, jj);

            // fold amplitude+sign into the hann coefficients (4 muls/image):
            // tap value = (p0 + pc*cos + ps*(-sin)) / x
            const float a2s = a2 * sgn;
            const float p0  = 0.5f * a2s;
            const float pc  = hc * a2s;
            const float ps  = hs * a2s;
            const int   ib  = base + lane;

            {   // t = lane
                const float x = fr + tmf0;
                const float w = fmaf(pc, c0, fmaf(ps, ns0, p0));
                if ((unsigned)ib < RIR_LEN)
                    atomicAdd(&srir[ib], __fdividef(w, x));
            }
            {   // t = lane + 32
                const float x = fr + tmf1;
                const float w = fmaf(pc, c1, fmaf(ps, ns1, p0));
                if ((unsigned)(ib + 32) < RIR_LEN)
                    atomicAdd(&srir[ib + 32], __fdividef(w, x));
            }
            {   // t = lane + 64 (t=80 tap is identically zero -> lanes 0..15)
                const float x = fr + tmf2;
                const float w = fmaf(pc, c2, fmaf(ps, ns2, p0));
                if (lane < 16 && (unsigned)(ib + 64) < RIR_LEN)
                    atomicAdd(&srir[ib + 64], __fdividef(w, x));
            }
        }
    }
    __syncthreads();

    // RED.ADD this CTA's partial RIR into the output row (coalesced, no-return)
    {
        float* orow = out + (size_t)b * RIR_LEN;
        for (int i = tid; i < RIR_LEN; i += NTH)
            atomicAdd(&orow[i], srir[i]);
    }

    // TOA (single writer per room, plain store)
    if (sub == 0 && tid == 0) {
        const float d0 = micS[0] - srcS[0];
        const float d1 = micS[1] - srcS[1];
        const float d2 = micS[2] - srcS[2];
        out[(size_t)B * RIR_LEN + b] =
            40.0f + FS_OVER_C * sqrtf(d0 * d0 + d1 * d1 + d2 * d2);
    }
}

extern "C" void kernel_launch(void* const* d_in, const int* in_sizes, int n_in,
                              void* d_out, int out_size)
{
    const float* in  = (const float*)d_in[0];
    float*       out = (float*)d_out;
    const int B = in_sizes[0] / 10;          // 256 rooms x 10 params
    // zero RIR region via capturable memset node (TOA region overwritten later)
    cudaMemsetAsync(out, 0, (size_t)B * RIR_LEN * sizeof(float));
    rir_partial_kernel<<<B * NSPLIT, NTH>>>(in, out, B);
}